// round 12
// baseline (speedup 1.0000x reference)
#include <cuda_runtime.h>

#define BSZ   8
#define NN    20000
#define FIN   256
#define NH    8
#define ND    64
#define EE    160000

#define RPB   544        // rows per block (multiple of 128)
#define NBX   37         // ceil(20000/544)

typedef unsigned long long ull;

// Scratch (device globals — no allocation allowed)
__device__ float g_u[BSZ * 2 * NH * FIN];          // [b][s][h][f]  (o = s*8+h)
__device__ float g_scores[2][BSZ * NN * NH];       // [s][(b*N+n)*8+h]
__device__ int   g_idx_is64;

__device__ __forceinline__ void fma2(ull& d, ull a, ull b) {
    asm("fma.rn.f32x2 %0, %1, %2, %0;" : "+l"(d) : "l"(a), "l"(b));
}
__device__ __forceinline__ void upk2(ull v, float& lo, float& hi) {
    asm("mov.b64 {%0, %1}, %2;" : "=f"(lo), "=f"(hi) : "l"(v));
}

// ---------------------------------------------------------------------------
// K1: u[b][o][f] = sum_d W[h*64+d][f] * scoring_{s}[b][h][d],  o = s*8+h
// grid = 256 blocks: (b,s,h) x fhalf; block = 128 threads (one f each).
// Entire 64-element W column preloaded into registers under full unroll ->
// ~55+ outstanding LDGs per warp (was ~6 at 32 regs) -> one memory round trip.
// Block 0 warp 0 additionally sniffs index dtype (int64 -> odd words all 0).
// ---------------------------------------------------------------------------
__global__ void __launch_bounds__(128)
k_prep(const float* __restrict__ W,
       const float* __restrict__ src,
       const float* __restrict__ trg,
       const unsigned int* __restrict__ head_words) {
    if (blockIdx.x == 0 && threadIdx.x < 32) {
        unsigned int nz = 0;
        for (int i = threadIdx.x; i < 512; i += 32)
            nz |= head_words[2 * i + 1];
        nz = __reduce_or_sync(0xffffffffu, nz);
        if (threadIdx.x == 0) g_idx_is64 = (nz == 0u) ? 1 : 0;
    }

    const int blk   = blockIdx.x;
    const int fhalf = blk & 1;
    const int grp   = blk >> 1;          // (b*2+s)*8 + h
    const int h     = grp & 7;
    const int s     = (grp >> 3) & 1;
    const int b     = grp >> 4;
    const int f     = fhalf * 128 + threadIdx.x;

    __shared__ float sc[ND];
    const float* scp = (s == 0 ? src : trg) + (b * NH + h) * ND;
    if (threadIdx.x < ND) sc[threadIdx.x] = scp[threadIdx.x];
    __syncthreads();

    const float* Wp = W + (h * ND) * FIN + f;

    // Preload the entire W column: 64 independent LDGs in flight.
    float wv[ND];
#pragma unroll
    for (int d = 0; d < ND; d++) wv[d] = Wp[d * FIN];

    float a0 = 0.f, a1 = 0.f, a2 = 0.f, a3 = 0.f;
#pragma unroll
    for (int d = 0; d < ND; d += 4) {
        a0 = fmaf(wv[d + 0], sc[d + 0], a0);
        a1 = fmaf(wv[d + 1], sc[d + 1], a1);
        a2 = fmaf(wv[d + 2], sc[d + 2], a2);
        a3 = fmaf(wv[d + 3], sc[d + 3], a3);
    }
    g_u[grp * FIN + f] = (a0 + a1) + (a2 + a3);
}

// ---------------------------------------------------------------------------
// K2: scores[(b,n,o)] = sum_f ch[b][n][f] * u[b][o][f]
// (R3 kernel verbatim — best measured)
// ---------------------------------------------------------------------------
__global__ void __launch_bounds__(256, 2)
k_scores(const float* __restrict__ ch) {
    __shared__ float4 u_s[16 * 64];
    const int b = blockIdx.y;

    // Load u[b] once per block, swizzled: idx = o*64 + fq*32 + (fi4 ^ (o>>2) ^ (fq<<2))
    for (int e = threadIdx.x; e < 1024; e += 256) {
        int o = e >> 6, f4 = e & 63;
        int fqf = f4 >> 5, fi4 = f4 & 31;
        float4 v = *(const float4*)(g_u + ((b * 16 + o) << 8) + (f4 << 2));
        u_s[(o << 6) + (fqf << 5) + (fi4 ^ (o >> 2) ^ (fqf << 2))] = v;
    }
    __syncthreads();

    const int w    = threadIdx.x >> 5;
    const int lane = threadIdx.x & 31;
    const int og   = lane & 3;
    const int rl   = (lane >> 2) & 3;
    const int fq   = lane >> 4;

    const int r0   = blockIdx.x * RPB;
    const int rend = (r0 + RPB < NN) ? r0 + RPB : NN;

    const float* chb = ch + (size_t)b * NN * FIN + fq * 128;
    const ulonglong2* us = (const ulonglong2*)u_s;

    const int mask = og ^ (fq << 2);
    int ub0 = (og * 4 + 0) * 64 + fq * 32;
    int ub1 = (og * 4 + 1) * 64 + fq * 32;
    int ub2 = (og * 4 + 2) * 64 + fq * 32;
    int ub3 = (og * 4 + 3) * 64 + fq * 32;

    for (int rowbase = r0 + w * 16; rowbase < rend; rowbase += 128) {
        int row0 = rowbase + 0 * 4 + rl;
        int row1 = rowbase + 1 * 4 + rl;
        int row2 = rowbase + 2 * 4 + rl;
        int row3 = rowbase + 3 * 4 + rl;
        const ulonglong2* p0 = (const ulonglong2*)(chb + (size_t)(row0 < NN ? row0 : NN - 1) * FIN);
        const ulonglong2* p1 = (const ulonglong2*)(chb + (size_t)(row1 < NN ? row1 : NN - 1) * FIN);
        const ulonglong2* p2 = (const ulonglong2*)(chb + (size_t)(row2 < NN ? row2 : NN - 1) * FIN);
        const ulonglong2* p3 = (const ulonglong2*)(chb + (size_t)(row3 < NN ? row3 : NN - 1) * FIN);

        ull acc[4][4];
#pragma unroll
        for (int j = 0; j < 4; j++)
#pragma unroll
            for (int i = 0; i < 4; i++) acc[j][i] = 0ull;

#pragma unroll 8
        for (int fi4 = 0; fi4 < 32; fi4++) {
            ulonglong2 c0 = p0[fi4];
            ulonglong2 c1 = p1[fi4];
            ulonglong2 c2 = p2[fi4];
            ulonglong2 c3 = p3[fi4];
            int sx = fi4 ^ mask;
            ulonglong2 u0 = us[ub0 + sx];
            ulonglong2 u1 = us[ub1 + sx];
            ulonglong2 u2 = us[ub2 + sx];
            ulonglong2 u3 = us[ub3 + sx];

            fma2(acc[0][0], c0.x, u0.x); fma2(acc[0][0], c0.y, u0.y);
            fma2(acc[0][1], c0.x, u1.x); fma2(acc[0][1], c0.y, u1.y);
            fma2(acc[0][2], c0.x, u2.x); fma2(acc[0][2], c0.y, u2.y);
            fma2(acc[0][3], c0.x, u3.x); fma2(acc[0][3], c0.y, u3.y);

            fma2(acc[1][0], c1.x, u0.x); fma2(acc[1][0], c1.y, u0.y);
            fma2(acc[1][1], c1.x, u1.x); fma2(acc[1][1], c1.y, u1.y);
            fma2(acc[1][2], c1.x, u2.x); fma2(acc[1][2], c1.y, u2.y);
            fma2(acc[1][3], c1.x, u3.x); fma2(acc[1][3], c1.y, u3.y);

            fma2(acc[2][0], c2.x, u0.x); fma2(acc[2][0], c2.y, u0.y);
            fma2(acc[2][1], c2.x, u1.x); fma2(acc[2][1], c2.y, u1.y);
            fma2(acc[2][2], c2.x, u2.x); fma2(acc[2][2], c2.y, u2.y);
            fma2(acc[2][3], c2.x, u3.x); fma2(acc[2][3], c2.y, u3.y);

            fma2(acc[3][0], c3.x, u0.x); fma2(acc[3][0], c3.y, u0.y);
            fma2(acc[3][1], c3.x, u1.x); fma2(acc[3][1], c3.y, u1.y);
            fma2(acc[3][2], c3.x, u2.x); fma2(acc[3][2], c3.y, u2.y);
            fma2(acc[3][3], c3.x, u3.x); fma2(acc[3][3], c3.y, u3.y);
        }

        const int s_tab = og >> 1;
        const int hoff  = (og & 1) * 4;
        int rows[4] = {row0, row1, row2, row3};
#pragma unroll
        for (int j = 0; j < 4; j++) {
            float v[4];
#pragma unroll
            for (int i = 0; i < 4; i++) {
                float lo, hi; upk2(acc[j][i], lo, hi);
                v[i] = lo + hi;
            }
#pragma unroll
            for (int i = 0; i < 4; i++)
                v[i] += __shfl_xor_sync(0xffffffffu, v[i], 16);
            if (fq == 0 && rows[j] < NN) {
                float4 o4 = make_float4(v[0], v[1], v[2], v[3]);
                *(float4*)&g_scores[s_tab][((size_t)b * NN + rows[j]) * NH + hoff] = o4;
            }
        }
    }
}

// ---------------------------------------------------------------------------
// K3: out[i] = sigmoid(scores_src[head[i]] + scores_trg[tail[i]])
// 4 edges per thread (best measured variant).
// ---------------------------------------------------------------------------
__global__ void k_gather(const void* __restrict__ head,
                         const void* __restrict__ tail,
                         float* __restrict__ out, int total) {
    int i = blockIdx.x * blockDim.x + threadIdx.x;   // edge group of 4
    if (i * 4 >= total) return;

    long long h[4], t[4];
    if (g_idx_is64) {
        longlong2 a0 = ((const longlong2*)head)[2 * i];
        longlong2 a1 = ((const longlong2*)head)[2 * i + 1];
        longlong2 b0 = ((const longlong2*)tail)[2 * i];
        longlong2 b1 = ((const longlong2*)tail)[2 * i + 1];
        h[0] = a0.x; h[1] = a0.y; h[2] = a1.x; h[3] = a1.y;
        t[0] = b0.x; t[1] = b0.y; t[2] = b1.x; t[3] = b1.y;
    } else {
        int4 a = ((const int4*)head)[i];
        int4 c = ((const int4*)tail)[i];
        h[0] = a.x; h[1] = a.y; h[2] = a.z; h[3] = a.w;
        t[0] = c.x; t[1] = c.y; t[2] = c.z; t[3] = c.w;
    }

    float x[4];
#pragma unroll
    for (int k = 0; k < 4; k++)
        x[k] = g_scores[0][h[k]] + g_scores[1][t[k]];

    float4 r;
    r.x = 1.f / (1.f + __expf(-x[0]));
    r.y = 1.f / (1.f + __expf(-x[1]));
    r.z = 1.f / (1.f + __expf(-x[2]));
    r.w = 1.f / (1.f + __expf(-x[3]));
    ((float4*)out)[i] = r;
}

// ---------------------------------------------------------------------------
extern "C" void kernel_launch(void* const* d_in, const int* in_sizes, int n_in,
                              void* d_out, int out_size) {
    const float* ch   = (const float*)d_in[0];
    const void*  head = d_in[1];
    const void*  tail = d_in[2];
    const float* W    = (const float*)d_in[3];
    const float* src  = (const float*)d_in[4];
    const float* trg  = (const float*)d_in[5];
    float* out = (float*)d_out;

    k_prep<<<BSZ * 2 * NH * 2, 128>>>(W, src, trg, (const unsigned int*)head);

    dim3 g2(NBX, BSZ);
    k_scores<<<g2, 256>>>(ch);

    int total = BSZ * EE;                       // 1,280,000 (multiple of 4)
    int groups = total / 4;
    k_gather<<<(groups + 255) / 256, 256>>>(head, tail, out, total);
}

// round 13
// speedup vs baseline: 1.0436x; 1.0436x over previous
#include <cuda_runtime.h>

#define BSZ   8
#define NN    20000
#define FIN   256
#define NH    8
#define ND    64
#define EE    160000

#define RPB   544        // rows per block (multiple of 128)
#define NBX   37         // ceil(20000/544)

typedef unsigned long long ull;

// Scratch (device globals — no allocation allowed)
__device__ float g_u[BSZ * 2 * NH * FIN];          // [b][s][h][f]  (o = s*8+h)
__device__ float g_scores[2][BSZ * NN * NH];       // [s][(b*N+n)*8+h]
__device__ int   g_idx_is64;

__device__ __forceinline__ void fma2(ull& d, ull a, ull b) {
    asm("fma.rn.f32x2 %0, %1, %2, %0;" : "+l"(d) : "l"(a), "l"(b));
}
__device__ __forceinline__ void upk2(ull v, float& lo, float& hi) {
    asm("mov.b64 {%0, %1}, %2;" : "=f"(lo), "=f"(hi) : "l"(v));
}

// ---------------------------------------------------------------------------
// K1: u[b][o][f] = sum_d W[h*64+d][f] * scoring_{s}[b][h][d],  o = s*8+h
// One block per (b,s,h). W h-slice staged through smem in 4 tiles of 16 rows:
// tile copy is LINEAR float4 (coalesced, 4 independent LDG.128/thread ->
// structural MLP that ptxas cannot serialize), compute is conflict-free LDS.
// Block 0 warp 0 additionally sniffs index dtype (int64 -> odd words all 0).
// ---------------------------------------------------------------------------
__global__ void __launch_bounds__(256)
k_prep(const float* __restrict__ W,
       const float* __restrict__ src,
       const float* __restrict__ trg,
       const unsigned int* __restrict__ head_words) {
    if (blockIdx.x == 0 && threadIdx.x < 32) {
        unsigned int nz = 0;
        for (int i = threadIdx.x; i < 512; i += 32)
            nz |= head_words[2 * i + 1];
        nz = __reduce_or_sync(0xffffffffu, nz);
        if (threadIdx.x == 0) g_idx_is64 = (nz == 0u) ? 1 : 0;
    }

    const int grp = blockIdx.x;          // (b*2+s)*8 + h
    const int h   = grp & 7;
    const int s   = (grp >> 3) & 1;
    const int b   = grp >> 4;
    const int f   = threadIdx.x;

    __shared__ float sc[ND];
    __shared__ float4 Wt[16 * 64];       // 16 W-rows x 256 floats = 16 KB

    const float* scp = (s == 0 ? src : trg) + (b * NH + h) * ND;
    if (threadIdx.x < ND) sc[threadIdx.x] = scp[threadIdx.x];

    const float4* Wbase = (const float4*)(W + (size_t)(h * ND) * FIN);

    float acc = 0.f;
#pragma unroll 1
    for (int tile = 0; tile < 4; tile++) {
        // Stage rows [tile*16, tile*16+16): 1024 float4, linear & coalesced.
        const float4* src4 = Wbase + tile * 16 * (FIN / 4);
        __syncthreads();                 // protect Wt from previous iteration
#pragma unroll
        for (int e = 0; e < 4; e++)
            Wt[threadIdx.x + e * 256] = src4[threadIdx.x + e * 256];
        __syncthreads();

        const float* Ws = (const float*)Wt;
        const int d0 = tile * 16;
#pragma unroll
        for (int dd = 0; dd < 16; dd += 4) {
            float w0 = Ws[(dd + 0) * FIN + f];
            float w1 = Ws[(dd + 1) * FIN + f];
            float w2 = Ws[(dd + 2) * FIN + f];
            float w3 = Ws[(dd + 3) * FIN + f];
            acc = fmaf(w0, sc[d0 + dd + 0], acc);
            acc = fmaf(w1, sc[d0 + dd + 1], acc);
            acc = fmaf(w2, sc[d0 + dd + 2], acc);
            acc = fmaf(w3, sc[d0 + dd + 3], acc);
        }
    }
    g_u[grp * FIN + f] = acc;
}

// ---------------------------------------------------------------------------
// K2: scores[(b,n,o)] = sum_f ch[b][n][f] * u[b][o][f]
// (R3 kernel verbatim — best measured)
// ---------------------------------------------------------------------------
__global__ void __launch_bounds__(256, 2)
k_scores(const float* __restrict__ ch) {
    __shared__ float4 u_s[16 * 64];
    const int b = blockIdx.y;

    // Load u[b] once per block, swizzled: idx = o*64 + fq*32 + (fi4 ^ (o>>2) ^ (fq<<2))
    for (int e = threadIdx.x; e < 1024; e += 256) {
        int o = e >> 6, f4 = e & 63;
        int fqf = f4 >> 5, fi4 = f4 & 31;
        float4 v = *(const float4*)(g_u + ((b * 16 + o) << 8) + (f4 << 2));
        u_s[(o << 6) + (fqf << 5) + (fi4 ^ (o >> 2) ^ (fqf << 2))] = v;
    }
    __syncthreads();

    const int w    = threadIdx.x >> 5;
    const int lane = threadIdx.x & 31;
    const int og   = lane & 3;
    const int rl   = (lane >> 2) & 3;
    const int fq   = lane >> 4;

    const int r0   = blockIdx.x * RPB;
    const int rend = (r0 + RPB < NN) ? r0 + RPB : NN;

    const float* chb = ch + (size_t)b * NN * FIN + fq * 128;
    const ulonglong2* us = (const ulonglong2*)u_s;

    const int mask = og ^ (fq << 2);
    int ub0 = (og * 4 + 0) * 64 + fq * 32;
    int ub1 = (og * 4 + 1) * 64 + fq * 32;
    int ub2 = (og * 4 + 2) * 64 + fq * 32;
    int ub3 = (og * 4 + 3) * 64 + fq * 32;

    for (int rowbase = r0 + w * 16; rowbase < rend; rowbase += 128) {
        int row0 = rowbase + 0 * 4 + rl;
        int row1 = rowbase + 1 * 4 + rl;
        int row2 = rowbase + 2 * 4 + rl;
        int row3 = rowbase + 3 * 4 + rl;
        const ulonglong2* p0 = (const ulonglong2*)(chb + (size_t)(row0 < NN ? row0 : NN - 1) * FIN);
        const ulonglong2* p1 = (const ulonglong2*)(chb + (size_t)(row1 < NN ? row1 : NN - 1) * FIN);
        const ulonglong2* p2 = (const ulonglong2*)(chb + (size_t)(row2 < NN ? row2 : NN - 1) * FIN);
        const ulonglong2* p3 = (const ulonglong2*)(chb + (size_t)(row3 < NN ? row3 : NN - 1) * FIN);

        ull acc[4][4];
#pragma unroll
        for (int j = 0; j < 4; j++)
#pragma unroll
            for (int i = 0; i < 4; i++) acc[j][i] = 0ull;

#pragma unroll 8
        for (int fi4 = 0; fi4 < 32; fi4++) {
            ulonglong2 c0 = p0[fi4];
            ulonglong2 c1 = p1[fi4];
            ulonglong2 c2 = p2[fi4];
            ulonglong2 c3 = p3[fi4];
            int sx = fi4 ^ mask;
            ulonglong2 u0 = us[ub0 + sx];
            ulonglong2 u1 = us[ub1 + sx];
            ulonglong2 u2 = us[ub2 + sx];
            ulonglong2 u3 = us[ub3 + sx];

            fma2(acc[0][0], c0.x, u0.x); fma2(acc[0][0], c0.y, u0.y);
            fma2(acc[0][1], c0.x, u1.x); fma2(acc[0][1], c0.y, u1.y);
            fma2(acc[0][2], c0.x, u2.x); fma2(acc[0][2], c0.y, u2.y);
            fma2(acc[0][3], c0.x, u3.x); fma2(acc[0][3], c0.y, u3.y);

            fma2(acc[1][0], c1.x, u0.x); fma2(acc[1][0], c1.y, u0.y);
            fma2(acc[1][1], c1.x, u1.x); fma2(acc[1][1], c1.y, u1.y);
            fma2(acc[1][2], c1.x, u2.x); fma2(acc[1][2], c1.y, u2.y);
            fma2(acc[1][3], c1.x, u3.x); fma2(acc[1][3], c1.y, u3.y);

            fma2(acc[2][0], c2.x, u0.x); fma2(acc[2][0], c2.y, u0.y);
            fma2(acc[2][1], c2.x, u1.x); fma2(acc[2][1], c2.y, u1.y);
            fma2(acc[2][2], c2.x, u2.x); fma2(acc[2][2], c2.y, u2.y);
            fma2(acc[2][3], c2.x, u3.x); fma2(acc[2][3], c2.y, u3.y);

            fma2(acc[3][0], c3.x, u0.x); fma2(acc[3][0], c3.y, u0.y);
            fma2(acc[3][1], c3.x, u1.x); fma2(acc[3][1], c3.y, u1.y);
            fma2(acc[3][2], c3.x, u2.x); fma2(acc[3][2], c3.y, u2.y);
            fma2(acc[3][3], c3.x, u3.x); fma2(acc[3][3], c3.y, u3.y);
        }

        const int s_tab = og >> 1;
        const int hoff  = (og & 1) * 4;
        int rows[4] = {row0, row1, row2, row3};
#pragma unroll
        for (int j = 0; j < 4; j++) {
            float v[4];
#pragma unroll
            for (int i = 0; i < 4; i++) {
                float lo, hi; upk2(acc[j][i], lo, hi);
                v[i] = lo + hi;
            }
#pragma unroll
            for (int i = 0; i < 4; i++)
                v[i] += __shfl_xor_sync(0xffffffffu, v[i], 16);
            if (fq == 0 && rows[j] < NN) {
                float4 o4 = make_float4(v[0], v[1], v[2], v[3]);
                *(float4*)&g_scores[s_tab][((size_t)b * NN + rows[j]) * NH + hoff] = o4;
            }
        }
    }
}

// ---------------------------------------------------------------------------
// K3: out[i] = sigmoid(scores_src[head[i]] + scores_trg[tail[i]])
// 4 edges per thread (best measured variant).
// ---------------------------------------------------------------------------
__global__ void k_gather(const void* __restrict__ head,
                         const void* __restrict__ tail,
                         float* __restrict__ out, int total) {
    int i = blockIdx.x * blockDim.x + threadIdx.x;   // edge group of 4
    if (i * 4 >= total) return;

    long long h[4], t[4];
    if (g_idx_is64) {
        longlong2 a0 = ((const longlong2*)head)[2 * i];
        longlong2 a1 = ((const longlong2*)head)[2 * i + 1];
        longlong2 b0 = ((const longlong2*)tail)[2 * i];
        longlong2 b1 = ((const longlong2*)tail)[2 * i + 1];
        h[0] = a0.x; h[1] = a0.y; h[2] = a1.x; h[3] = a1.y;
        t[0] = b0.x; t[1] = b0.y; t[2] = b1.x; t[3] = b1.y;
    } else {
        int4 a = ((const int4*)head)[i];
        int4 c = ((const int4*)tail)[i];
        h[0] = a.x; h[1] = a.y; h[2] = a.z; h[3] = a.w;
        t[0] = c.x; t[1] = c.y; t[2] = c.z; t[3] = c.w;
    }

    float x[4];
#pragma unroll
    for (int k = 0; k < 4; k++)
        x[k] = g_scores[0][h[k]] + g_scores[1][t[k]];

    float4 r;
    r.x = 1.f / (1.f + __expf(-x[0]));
    r.y = 1.f / (1.f + __expf(-x[1]));
    r.z = 1.f / (1.f + __expf(-x[2]));
    r.w = 1.f / (1.f + __expf(-x[3]));
    ((float4*)out)[i] = r;
}

// ---------------------------------------------------------------------------
extern "C" void kernel_launch(void* const* d_in, const int* in_sizes, int n_in,
                              void* d_out, int out_size) {
    const float* ch   = (const float*)d_in[0];
    const void*  head = d_in[1];
    const void*  tail = d_in[2];
    const float* W    = (const float*)d_in[3];
    const float* src  = (const float*)d_in[4];
    const float* trg  = (const float*)d_in[5];
    float* out = (float*)d_out;

    k_prep<<<BSZ * 2 * NH, 256>>>(W, src, trg, (const unsigned int*)head);

    dim3 g2(NBX, BSZ);
    k_scores<<<g2, 256>>>(ch);

    int total = BSZ * EE;                       // 1,280,000 (multiple of 4)
    int groups = total / 4;
    k_gather<<<(groups + 255) / 256, 256>>>(head, tail, out, total);
}

// round 14
// speedup vs baseline: 1.0440x; 1.0004x over previous
#include <cuda_runtime.h>

#define BSZ   8
#define NN    20000
#define FIN   256
#define NH    8
#define ND    64
#define EE    160000

#define RPB   544        // rows per block (multiple of 128)
#define NBX   37         // ceil(20000/544)

typedef unsigned long long ull;

// Scratch (device globals — no allocation allowed)
__device__ float g_u[BSZ * 2 * NH * FIN];          // [b][s][h][f]  (o = s*8+h)
__device__ float g_scores[2][BSZ * NN * NH];       // [s][(b*N+n)*8+h]
__device__ int   g_idx_is64;

__device__ __forceinline__ void fma2(ull& d, ull a, ull b) {
    asm("fma.rn.f32x2 %0, %1, %2, %0;" : "+l"(d) : "l"(a), "l"(b));
}
__device__ __forceinline__ void upk2(ull v, float& lo, float& hi) {
    asm("mov.b64 {%0, %1}, %2;" : "=f"(lo), "=f"(hi) : "l"(v));
}

// ---------------------------------------------------------------------------
// K1: u[b][o][f] = sum_d W[h*64+d][f] * scoring_{s}[b][h][d],  o = s*8+h
// grid = 512: one block per (b,s,h) x f-quarter. Each block stages its
// 64-row x 64-float W quarter (16KB) in ONE shot (4 independent LDG.128 per
// thread, no serial tiles), one sync, then 64 threads compute one u each.
// One memory round-trip per block; 3-4 blocks/SM overlap the latency.
// Block 0 warp 0 additionally sniffs index dtype (int64 -> odd words all 0).
// ---------------------------------------------------------------------------
__global__ void __launch_bounds__(256)
k_prep(const float* __restrict__ W,
       const float* __restrict__ src,
       const float* __restrict__ trg,
       const unsigned int* __restrict__ head_words) {
    if (blockIdx.x == 0 && threadIdx.x < 32) {
        unsigned int nz = 0;
        for (int i = threadIdx.x; i < 512; i += 32)
            nz |= head_words[2 * i + 1];
        nz = __reduce_or_sync(0xffffffffu, nz);
        if (threadIdx.x == 0) g_idx_is64 = (nz == 0u) ? 1 : 0;
    }

    const int blk = blockIdx.x;
    const int fq  = blk & 3;             // f-quarter (64 floats)
    const int grp = blk >> 2;            // (b*2+s)*8 + h
    const int h   = grp & 7;
    const int s   = (grp >> 3) & 1;
    const int b   = grp >> 4;
    const int t   = threadIdx.x;

    __shared__ float  sc[ND];
    __shared__ float4 Wt4[1024];         // [d][16] float4 = 64 rows x 64 floats

    const float* scp = (s == 0 ? src : trg) + (b * NH + h) * ND;
    if (t < ND) sc[t] = scp[t];

    // Stage all 64 rows of this f-quarter: 1024 float4, 4 per thread,
    // all independent -> single round trip.
    const float4* Wb = (const float4*)W;
#pragma unroll
    for (int k = 0; k < 4; k++) {
        int e = t + k * 256;             // e = d*16 + j
        int d = e >> 4, j = e & 15;
        Wt4[e] = Wb[(size_t)(h * ND + d) * 64 + fq * 16 + j];
    }
    __syncthreads();

    if (t < 64) {
        const float* Ws = (const float*)Wt4;   // [d][64]
        float a0 = 0.f, a1 = 0.f, a2 = 0.f, a3 = 0.f;
#pragma unroll
        for (int d = 0; d < ND; d += 4) {
            a0 = fmaf(Ws[(d + 0) * 64 + t], sc[d + 0], a0);
            a1 = fmaf(Ws[(d + 1) * 64 + t], sc[d + 1], a1);
            a2 = fmaf(Ws[(d + 2) * 64 + t], sc[d + 2], a2);
            a3 = fmaf(Ws[(d + 3) * 64 + t], sc[d + 3], a3);
        }
        g_u[grp * FIN + fq * 64 + t] = (a0 + a1) + (a2 + a3);
    }
}

// ---------------------------------------------------------------------------
// K2: scores[(b,n,o)] = sum_f ch[b][n][f] * u[b][o][f]
// (R3 kernel verbatim — best measured)
// ---------------------------------------------------------------------------
__global__ void __launch_bounds__(256, 2)
k_scores(const float* __restrict__ ch) {
    __shared__ float4 u_s[16 * 64];
    const int b = blockIdx.y;

    // Load u[b] once per block, swizzled: idx = o*64 + fq*32 + (fi4 ^ (o>>2) ^ (fq<<2))
    for (int e = threadIdx.x; e < 1024; e += 256) {
        int o = e >> 6, f4 = e & 63;
        int fqf = f4 >> 5, fi4 = f4 & 31;
        float4 v = *(const float4*)(g_u + ((b * 16 + o) << 8) + (f4 << 2));
        u_s[(o << 6) + (fqf << 5) + (fi4 ^ (o >> 2) ^ (fqf << 2))] = v;
    }
    __syncthreads();

    const int w    = threadIdx.x >> 5;
    const int lane = threadIdx.x & 31;
    const int og   = lane & 3;
    const int rl   = (lane >> 2) & 3;
    const int fq   = lane >> 4;

    const int r0   = blockIdx.x * RPB;
    const int rend = (r0 + RPB < NN) ? r0 + RPB : NN;

    const float* chb = ch + (size_t)b * NN * FIN + fq * 128;
    const ulonglong2* us = (const ulonglong2*)u_s;

    const int mask = og ^ (fq << 2);
    int ub0 = (og * 4 + 0) * 64 + fq * 32;
    int ub1 = (og * 4 + 1) * 64 + fq * 32;
    int ub2 = (og * 4 + 2) * 64 + fq * 32;
    int ub3 = (og * 4 + 3) * 64 + fq * 32;

    for (int rowbase = r0 + w * 16; rowbase < rend; rowbase += 128) {
        int row0 = rowbase + 0 * 4 + rl;
        int row1 = rowbase + 1 * 4 + rl;
        int row2 = rowbase + 2 * 4 + rl;
        int row3 = rowbase + 3 * 4 + rl;
        const ulonglong2* p0 = (const ulonglong2*)(chb + (size_t)(row0 < NN ? row0 : NN - 1) * FIN);
        const ulonglong2* p1 = (const ulonglong2*)(chb + (size_t)(row1 < NN ? row1 : NN - 1) * FIN);
        const ulonglong2* p2 = (const ulonglong2*)(chb + (size_t)(row2 < NN ? row2 : NN - 1) * FIN);
        const ulonglong2* p3 = (const ulonglong2*)(chb + (size_t)(row3 < NN ? row3 : NN - 1) * FIN);

        ull acc[4][4];
#pragma unroll
        for (int j = 0; j < 4; j++)
#pragma unroll
            for (int i = 0; i < 4; i++) acc[j][i] = 0ull;

#pragma unroll 8
        for (int fi4 = 0; fi4 < 32; fi4++) {
            ulonglong2 c0 = p0[fi4];
            ulonglong2 c1 = p1[fi4];
            ulonglong2 c2 = p2[fi4];
            ulonglong2 c3 = p3[fi4];
            int sx = fi4 ^ mask;
            ulonglong2 u0 = us[ub0 + sx];
            ulonglong2 u1 = us[ub1 + sx];
            ulonglong2 u2 = us[ub2 + sx];
            ulonglong2 u3 = us[ub3 + sx];

            fma2(acc[0][0], c0.x, u0.x); fma2(acc[0][0], c0.y, u0.y);
            fma2(acc[0][1], c0.x, u1.x); fma2(acc[0][1], c0.y, u1.y);
            fma2(acc[0][2], c0.x, u2.x); fma2(acc[0][2], c0.y, u2.y);
            fma2(acc[0][3], c0.x, u3.x); fma2(acc[0][3], c0.y, u3.y);

            fma2(acc[1][0], c1.x, u0.x); fma2(acc[1][0], c1.y, u0.y);
            fma2(acc[1][1], c1.x, u1.x); fma2(acc[1][1], c1.y, u1.y);
            fma2(acc[1][2], c1.x, u2.x); fma2(acc[1][2], c1.y, u2.y);
            fma2(acc[1][3], c1.x, u3.x); fma2(acc[1][3], c1.y, u3.y);

            fma2(acc[2][0], c2.x, u0.x); fma2(acc[2][0], c2.y, u0.y);
            fma2(acc[2][1], c2.x, u1.x); fma2(acc[2][1], c2.y, u1.y);
            fma2(acc[2][2], c2.x, u2.x); fma2(acc[2][2], c2.y, u2.y);
            fma2(acc[2][3], c2.x, u3.x); fma2(acc[2][3], c2.y, u3.y);

            fma2(acc[3][0], c3.x, u0.x); fma2(acc[3][0], c3.y, u0.y);
            fma2(acc[3][1], c3.x, u1.x); fma2(acc[3][1], c3.y, u1.y);
            fma2(acc[3][2], c3.x, u2.x); fma2(acc[3][2], c3.y, u2.y);
            fma2(acc[3][3], c3.x, u3.x); fma2(acc[3][3], c3.y, u3.y);
        }

        const int s_tab = og >> 1;
        const int hoff  = (og & 1) * 4;
        int rows[4] = {row0, row1, row2, row3};
#pragma unroll
        for (int j = 0; j < 4; j++) {
            float v[4];
#pragma unroll
            for (int i = 0; i < 4; i++) {
                float lo, hi; upk2(acc[j][i], lo, hi);
                v[i] = lo + hi;
            }
#pragma unroll
            for (int i = 0; i < 4; i++)
                v[i] += __shfl_xor_sync(0xffffffffu, v[i], 16);
            if (fq == 0 && rows[j] < NN) {
                float4 o4 = make_float4(v[0], v[1], v[2], v[3]);
                *(float4*)&g_scores[s_tab][((size_t)b * NN + rows[j]) * NH + hoff] = o4;
            }
        }
    }
}

// ---------------------------------------------------------------------------
// K3: out[i] = sigmoid(scores_src[head[i]] + scores_trg[tail[i]])
// 4 edges per thread (best measured variant).
// ---------------------------------------------------------------------------
__global__ void k_gather(const void* __restrict__ head,
                         const void* __restrict__ tail,
                         float* __restrict__ out, int total) {
    int i = blockIdx.x * blockDim.x + threadIdx.x;   // edge group of 4
    if (i * 4 >= total) return;

    long long h[4], t[4];
    if (g_idx_is64) {
        longlong2 a0 = ((const longlong2*)head)[2 * i];
        longlong2 a1 = ((const longlong2*)head)[2 * i + 1];
        longlong2 b0 = ((const longlong2*)tail)[2 * i];
        longlong2 b1 = ((const longlong2*)tail)[2 * i + 1];
        h[0] = a0.x; h[1] = a0.y; h[2] = a1.x; h[3] = a1.y;
        t[0] = b0.x; t[1] = b0.y; t[2] = b1.x; t[3] = b1.y;
    } else {
        int4 a = ((const int4*)head)[i];
        int4 c = ((const int4*)tail)[i];
        h[0] = a.x; h[1] = a.y; h[2] = a.z; h[3] = a.w;
        t[0] = c.x; t[1] = c.y; t[2] = c.z; t[3] = c.w;
    }

    float x[4];
#pragma unroll
    for (int k = 0; k < 4; k++)
        x[k] = g_scores[0][h[k]] + g_scores[1][t[k]];

    float4 r;
    r.x = 1.f / (1.f + __expf(-x[0]));
    r.y = 1.f / (1.f + __expf(-x[1]));
    r.z = 1.f / (1.f + __expf(-x[2]));
    r.w = 1.f / (1.f + __expf(-x[3]));
    ((float4*)out)[i] = r;
}

// ---------------------------------------------------------------------------
extern "C" void kernel_launch(void* const* d_in, const int* in_sizes, int n_in,
                              void* d_out, int out_size) {
    const float* ch   = (const float*)d_in[0];
    const void*  head = d_in[1];
    const void*  tail = d_in[2];
    const float* W    = (const float*)d_in[3];
    const float* src  = (const float*)d_in[4];
    const float* trg  = (const float*)d_in[5];
    float* out = (float*)d_out;

    k_prep<<<BSZ * 2 * NH * 4, 256>>>(W, src, trg, (const unsigned int*)head);

    dim3 g2(NBX, BSZ);
    k_scores<<<g2, 256>>>(ch);

    int total = BSZ * EE;                       // 1,280,000 (multiple of 4)
    int groups = total / 4;
    k_gather<<<(groups + 255) / 256, 256>>>(head, tail, out, total);
}